// round 11
// baseline (speedup 1.0000x reference)
#include <cuda_runtime.h>
#include <cuda_bf16.h>
#include <cstdint>

// Problem constants
#define Cc      128
#define Hh      256
#define Ww      256
#define Bb      4
#define PLANE   65536
#define NPLANES 512
#define TOTAL   33554432

// Scratch (allocation-free rule: __device__ globals). 16B-aligned for uint4 IO.
__device__ __align__(16) __nv_bfloat16 g_h[TOTAL];
__device__ __align__(16) __nv_bfloat16 g_v[TOTAL];
__device__ float  g_hpart[NPLANES * 32];
__device__ float  g_vpart[NPLANES * 8];
__device__ float  g_gate[Bb * 2];

__device__ __forceinline__ uint32_t smem_u32(const void* p) {
    uint32_t a;
    asm("{ .reg .u64 t; cvta.to.shared.u64 t, %1; cvt.u32.u64 %0, t; }" : "=r"(a) : "l"(p));
    return a;
}

// ---------------------------------------------------------------------------
// Kernel 1: horizontal chain  h = dw1x5(x) then dw1x7 dil3 (bf16 output).
// One WARP per image row; ys zero-padded to match reference inter-stage pad.
// ---------------------------------------------------------------------------
__global__ __launch_bounds__(256) void hconv_kernel(
    const float* __restrict__ x,
    const float* __restrict__ h1w,
    const float* __restrict__ h2w)
{
    __shared__ float xs[8][280];
    __shared__ float ys[8][280];
    __shared__ float red[8];

    const int plane = blockIdx.y;
    const int rb    = blockIdx.x;
    const int c     = plane & (Cc - 1);
    const int l     = threadIdx.x;
    const int wrp   = threadIdx.y;
    const int row   = rb * 8 + wrp;

    float w1[5], w2[7];
#pragma unroll
    for (int j = 0; j < 5; j++) w1[j] = h1w[c * 5 + j];
#pragma unroll
    for (int k = 0; k < 7; k++) w2[k] = h2w[c * 7 + k];

    const int base = plane * PLANE + row * Ww;

    *(float4*)&xs[wrp][12 + 4 * l]  = *(const float4*)(x + base + 4 * l);
    *(float4*)&xs[wrp][140 + 4 * l] = *(const float4*)(x + base + 128 + 4 * l);
    if (l < 3) {
        *(float4*)&xs[wrp][4 * l]       = make_float4(0.f, 0.f, 0.f, 0.f);
        *(float4*)&xs[wrp][268 + 4 * l] = make_float4(0.f, 0.f, 0.f, 0.f);
    }
    if (l < 9)  ys[wrp][l] = 0.f;
    if (l < 11) ys[wrp][265 + l] = 0.f;
    __syncwarp();

#pragma unroll
    for (int q = 0; q < 8; q++) {
        const int i = 9 + l + 32 * q;
        float y = 0.f;
#pragma unroll
        for (int j = 0; j < 5; j++) y += xs[wrp][i + 1 + j] * w1[j];
        ys[wrp][i] = y;
    }
    __syncwarp();

    float acc = 0.f;
#pragma unroll
    for (int q = 0; q < 8; q++) {
        const int px = l + 32 * q;
        float v = 0.f;
#pragma unroll
        for (int k = 0; k < 7; k++) v += ys[wrp][px + 3 * k] * w2[k];
        g_h[base + px] = __float2bfloat16(v);
        acc += v;
    }

#pragma unroll
    for (int o = 16; o > 0; o >>= 1) acc += __shfl_down_sync(0xffffffffu, acc, o);
    if (l == 0) red[wrp] = acc;
    __syncthreads();
    if (wrp == 0 && l == 0) {
        float s = 0.f;
#pragma unroll
        for (int i = 0; i < 8; i++) s += red[i];
        g_hpart[plane * 32 + rb] = s;
    }
}

// ---------------------------------------------------------------------------
// Kernel 2: vertical chain, register sliding windows (bf16 output).
// ---------------------------------------------------------------------------
__global__ __launch_bounds__(256) void vconv_kernel(
    const float* __restrict__ x,
    const float* __restrict__ v1w,
    const float* __restrict__ v2w)
{
    const int t   = threadIdx.x;
    const int l   = t & 31;
    const int w   = t >> 5;
    const int idx = blockIdx.x * 8 + w;
    const int plane = idx >> 3;
    const int tile  = idx & 7;
    const int c     = plane & (Cc - 1);

    float w1[5], w2[7];
#pragma unroll
    for (int j = 0; j < 5; j++) w1[j] = v1w[c * 5 + j];
#pragma unroll
    for (int k = 0; k < 7; k++) w2[k] = v2w[c * 7 + k];

    const float* xp = x + plane * PLANE + tile * 32 + l;
    __nv_bfloat16* vout = g_v + plane * PLANE + tile * 32 + l;

    float Y[21];
    float X[7];
#pragma unroll
    for (int i = 0; i < 21; i++) Y[i] = 0.f;

    float xv[11];
#pragma unroll
    for (int r = 0; r < 11; r++) xv[r] = xp[r * Ww];
#pragma unroll
    for (int ry = 0; ry < 9; ry++) {
        float s = 0.f;
#pragma unroll
        for (int j = 0; j < 5; j++) {
            int q = ry + j - 2;
            if (q >= 0) s += xv[q] * w1[j];
        }
        Y[ry] = s;
    }
#pragma unroll
    for (int r = 7; r < 11; r++) X[r % 7] = xv[r];

    float accg = 0.f;

#pragma unroll 1
    for (int sb = 0; sb < 273; sb += 21) {
#pragma unroll
        for (int u = 0; u < 21; u++) {
            const int s = sb + u;
            const int xrow = s + 11;
            float xn = xp[(xrow < 256 ? xrow : 255) * Ww];
            if (xrow > 255) xn = 0.f;
            X[(u + 4) % 7] = xn;
            float yv = X[(u + 0) % 7] * w1[0] + X[(u + 1) % 7] * w1[1]
                     + X[(u + 2) % 7] * w1[2] + X[(u + 3) % 7] * w1[3]
                     + X[(u + 4) % 7] * w1[4];
            if (s + 9 > 255) yv = 0.f;
            Y[(u + 9) % 21] = yv;
            float v = Y[(u + 12) % 21] * w2[0] + Y[(u + 15) % 21] * w2[1]
                    + Y[(u + 18) % 21] * w2[2] + Y[(u + 0)  % 21] * w2[3]
                    + Y[(u + 3)  % 21] * w2[4] + Y[(u + 6)  % 21] * w2[5]
                    + Y[(u + 9)  % 21] * w2[6];
            if (s < 256) {
                vout[s * Ww] = __float2bfloat16(v);
                accg += v;
            }
        }
    }

#pragma unroll
    for (int o = 16; o > 0; o >>= 1) accg += __shfl_down_sync(0xffffffffu, accg, o);
    if (l == 0) g_vpart[idx] = accg;
}

// ---------------------------------------------------------------------------
// Kernel 3: gate (unchanged)
// ---------------------------------------------------------------------------
__global__ __launch_bounds__(256) void gate_kernel(
    const float* __restrict__ g1w,
    const float* __restrict__ g2w,
    const float* __restrict__ g2b)
{
    __shared__ float pooled[Bb][2 * Cc];
    __shared__ float gs[Bb][32];
    const int t = threadIdx.x;
    const float inv = 1.0f / 65536.0f;

    for (int p = t; p < NPLANES; p += 256) {
        int b = p >> 7, c = p & 127;
        float hs = 0.f;
#pragma unroll
        for (int i = 0; i < 32; i++) hs += g_hpart[p * 32 + i];
        float vs = 0.f;
#pragma unroll
        for (int i = 0; i < 8; i++) vs += g_vpart[p * 8 + i];
        pooled[b][c]      = hs * inv;
        pooled[b][Cc + c] = vs * inv;
    }
    __syncthreads();

    if (t < 128) {
        int b = t >> 5, j = t & 31;
        float s = 0.f;
        for (int i = 0; i < 2 * Cc; i++) s += pooled[b][i] * g1w[j * 256 + i];
        gs[b][j] = s / (1.0f + expf(-s));
    }
    __syncthreads();

    if (t < Bb) {
        int b = t;
        float l0 = g2b[0], l1 = g2b[1];
        for (int j = 0; j < 32; j++) {
            l0 += gs[b][j] * g2w[j];
            l1 += gs[b][j] * g2w[32 + j];
        }
        float m = fmaxf(l0, l1);
        float e0 = expf(l0 - m), e1 = expf(l1 - m);
        float d = e0 + e1;
        g_gate[b * 2 + 0] = e0 / d;
        g_gate[b * 2 + 1] = e1 / d;
    }
}

// ---------------------------------------------------------------------------
// Kernel 4: bf16 HMMA fuse via mma.sync.m16n8k16 (base ISA — no tcgen05).
// D[o,px] = fuse_w[o][c] * attn[c][px]; CTA tile 128o x 128px, K=128.
// 8 warps: warp (og,pg) computes 64o x 32px = 4x4 m16n8k16 tiles, 8 K-steps.
// A = wTs[o][c] bf16 row-major (ldmatrix.x4); B = as[c][px] bf16 row-major
// (ldmatrix.x2.trans -> col-major fragment). Pitch 136 bf16 (272 B): each
// ldmatrix row shifts 4 banks -> conflict-free.
// Epilogue: acc -> Dsm (reused smem, pitch 132) -> coalesced float4 IO.
// ---------------------------------------------------------------------------
#define FUSE_SMEM 69632

__global__ __launch_bounds__(256) void fuse_mma_kernel(
    const float* __restrict__ x,
    const float* __restrict__ fw,
    const float* __restrict__ fb,
    float* __restrict__ out)
{
    extern __shared__ __align__(16) char smem[];
    __nv_bfloat16* wTs = (__nv_bfloat16*)smem;            // [128][136]
    __nv_bfloat16* as  = (__nv_bfloat16*)(smem + 34816);  // [128][136]
    float* Dsm = (float*)smem;                            // [128][132] (reuse)

    const int t   = threadIdx.x;
    const int wid = t >> 5;
    const int l   = t & 31;
    const int b   = blockIdx.x >> 9;
    const int p0  = (blockIdx.x & 511) << 7;

    // ---- stage A = fuse_w (fp32 -> bf16, row-major [o][c], pitch 136)
    for (int i = t; i < 4096; i += 256) {
        const int o  = i >> 5;
        const int c4 = (i & 31) << 2;
        const float4 w4 = *(const float4*)(fw + o * 128 + c4);
        __nv_bfloat162 p01 = __floats2bfloat162_rn(w4.x, w4.y);
        __nv_bfloat162 p23 = __floats2bfloat162_rn(w4.z, w4.w);
        *(uint2*)(wTs + o * 136 + c4) =
            make_uint2(*(uint32_t*)&p01, *(uint32_t*)&p23);
    }

    // ---- stage B = attn = wh*h + wv*v (bf16, row-major [c][px], pitch 136)
    const float wh  = g_gate[2 * b + 0];
    const float wvv = g_gate[2 * b + 1];
    const int baseb = b * (Cc * PLANE) + p0;
    for (int i = t; i < 2048; i += 256) {
        const int c  = i >> 4;
        const int px = (i & 15) << 3;
        const uint4 H = *(const uint4*)(g_h + baseb + c * PLANE + px);
        const uint4 V = *(const uint4*)(g_v + baseb + c * PLANE + px);
        const uint32_t* hp = &H.x;
        const uint32_t* vp = &V.x;
        uint32_t rr[4];
#pragma unroll
        for (int u = 0; u < 4; u++) {
            float2 hf = __bfloat1622float2(*(const __nv_bfloat162*)&hp[u]);
            float2 vf = __bfloat1622float2(*(const __nv_bfloat162*)&vp[u]);
            __nv_bfloat162 a2 = __floats2bfloat162_rn(wh * hf.x + wvv * vf.x,
                                                      wh * hf.y + wvv * vf.y);
            rr[u] = *(uint32_t*)&a2;
        }
        *(uint4*)(as + c * 136 + px) = make_uint4(rr[0], rr[1], rr[2], rr[3]);
    }
    __syncthreads();

    // ---- warp tile: og in {0,64}, pg in {0,32,64,96}
    const int og = (wid >> 2) * 64;
    const int pg = (wid & 3) * 32;

    float acc[4][4][4];
#pragma unroll
    for (int mi = 0; mi < 4; mi++)
#pragma unroll
        for (int ni = 0; ni < 4; ni++)
#pragma unroll
            for (int q = 0; q < 4; q++) acc[mi][ni][q] = 0.f;

    // per-lane ldmatrix base addresses (k0 = 0)
    uint32_t aAddr[4], bAddr[4];
#pragma unroll
    for (int mi = 0; mi < 4; mi++)
        aAddr[mi] = smem_u32(wTs + (og + mi * 16 + (l & 15)) * 136 + (l >> 4) * 8);
#pragma unroll
    for (int ni = 0; ni < 4; ni++)
        bAddr[ni] = smem_u32(as + (l & 15) * 136 + pg + ni * 8);

#pragma unroll
    for (int kk = 0; kk < 8; kk++) {
        uint32_t a[4][4], bq[4][2];
#pragma unroll
        for (int mi = 0; mi < 4; mi++) {
            asm volatile("ldmatrix.sync.aligned.m8n8.x4.shared.b16 {%0,%1,%2,%3}, [%4];"
                : "=r"(a[mi][0]), "=r"(a[mi][1]), "=r"(a[mi][2]), "=r"(a[mi][3])
                : "r"(aAddr[mi] + kk * 32));
        }
#pragma unroll
        for (int ni = 0; ni < 4; ni++) {
            asm volatile("ldmatrix.sync.aligned.m8n8.x2.trans.shared.b16 {%0,%1}, [%2];"
                : "=r"(bq[ni][0]), "=r"(bq[ni][1])
                : "r"(bAddr[ni] + kk * 16 * 272));
        }
#pragma unroll
        for (int mi = 0; mi < 4; mi++)
#pragma unroll
            for (int ni = 0; ni < 4; ni++) {
                asm volatile(
                    "mma.sync.aligned.m16n8k16.row.col.f32.bf16.bf16.f32 "
                    "{%0,%1,%2,%3}, {%4,%5,%6,%7}, {%8,%9}, {%0,%1,%2,%3};"
                    : "+f"(acc[mi][ni][0]), "+f"(acc[mi][ni][1]),
                      "+f"(acc[mi][ni][2]), "+f"(acc[mi][ni][3])
                    : "r"(a[mi][0]), "r"(a[mi][1]), "r"(a[mi][2]), "r"(a[mi][3]),
                      "r"(bq[ni][0]), "r"(bq[ni][1]));
            }
    }
    __syncthreads();   // done reading wTs/as; reuse smem as Dsm

    // ---- acc fragments -> Dsm (pitch 132)
#pragma unroll
    for (int mi = 0; mi < 4; mi++) {
        const int row = og + mi * 16 + (l >> 2);
#pragma unroll
        for (int ni = 0; ni < 4; ni++) {
            const int col = pg + ni * 8 + (l & 3) * 2;
            *(float2*)(Dsm + row * 132 + col) =
                make_float2(acc[mi][ni][0], acc[mi][ni][1]);
            *(float2*)(Dsm + (row + 8) * 132 + col) =
                make_float2(acc[mi][ni][2], acc[mi][ni][3]);
        }
    }
    __syncthreads();

    // ---- epilogue: out = x * (0.5 + 0.5*(d + fb[o])), fully coalesced
    for (int o = wid; o < 128; o += 8) {
        const float4 d4 = *(const float4*)(Dsm + o * 132 + l * 4);
        const float fbv = fb[o];
        const int idx = b * (Cc * PLANE) + o * PLANE + p0 + l * 4;
        const float4 xv = *(const float4*)(x + idx);
        float4 r;
        r.x = xv.x * (0.5f + 0.5f * (d4.x + fbv));
        r.y = xv.y * (0.5f + 0.5f * (d4.y + fbv));
        r.z = xv.z * (0.5f + 0.5f * (d4.z + fbv));
        r.w = xv.w * (0.5f + 0.5f * (d4.w + fbv));
        *(float4*)(out + idx) = r;
    }
}

// ---------------------------------------------------------------------------
extern "C" void kernel_launch(void* const* d_in, const int* in_sizes, int n_in,
                              void* d_out, int out_size)
{
    const float* x   = (const float*)d_in[0];
    const float* h1w = (const float*)d_in[1];
    const float* h2w = (const float*)d_in[2];
    const float* v1w = (const float*)d_in[3];
    const float* v2w = (const float*)d_in[4];
    const float* g1w = (const float*)d_in[5];
    const float* g2w = (const float*)d_in[6];
    const float* g2b = (const float*)d_in[7];
    const float* fw  = (const float*)d_in[8];
    const float* fb  = (const float*)d_in[9];
    float* out = (float*)d_out;

    cudaFuncSetAttribute(fuse_mma_kernel, cudaFuncAttributeMaxDynamicSharedMemorySize, FUSE_SMEM);

    hconv_kernel<<<dim3(32, 512), dim3(32, 8)>>>(x, h1w, h2w);
    vconv_kernel<<<512, 256>>>(x, v1w, v2w);
    gate_kernel<<<1, 256>>>(g1w, g2w, g2b);
    fuse_mma_kernel<<<2048, 256, FUSE_SMEM>>>(x, fw, fb, out);
}

// round 12
// speedup vs baseline: 2.2364x; 2.2364x over previous
#include <cuda_runtime.h>
#include <cuda_bf16.h>
#include <cstdint>

// Problem constants
#define Cc      128
#define Hh      256
#define Ww      256
#define Bb      4
#define PLANE   65536
#define NPLANES 512
#define TOTAL   33554432

// Scratch (allocation-free rule: __device__ globals). 16B-aligned for uint4 IO.
__device__ __align__(16) __nv_bfloat16 g_h[TOTAL];
__device__ __align__(16) __nv_bfloat16 g_v[TOTAL];
__device__ float  g_hpart[NPLANES * 32];
__device__ float  g_vpart[NPLANES * 8];
__device__ float  g_gate[Bb * 2];

__device__ __forceinline__ uint32_t smem_u32(const void* p) {
    uint32_t a;
    asm("{ .reg .u64 t; cvta.to.shared.u64 t, %1; cvt.u32.u64 %0, t; }" : "=r"(a) : "l"(p));
    return a;
}

// ---------------------------------------------------------------------------
// Kernel 1: COMBINED directional convs. Blocks [0,512) run the vertical chain
// (pure-register sliding window, FFMA/LDG-bound); blocks [512, 16896) run the
// horizontal chain (smem, LDS-bound). Complementary pipes overlap on each SM;
// long-running vconv blocks launch first.
// Block: 256 threads flat.
// ---------------------------------------------------------------------------
__global__ __launch_bounds__(256) void conv_kernel(
    const float* __restrict__ x,
    const float* __restrict__ h1w,
    const float* __restrict__ h2w,
    const float* __restrict__ v1w,
    const float* __restrict__ v2w)
{
    __shared__ float xs[8][280];
    __shared__ float ys[8][280];
    __shared__ float red[8];

    const int bid = blockIdx.x;
    const int t   = threadIdx.x;
    const int l   = t & 31;
    const int wrp = t >> 5;

    if (bid < 512) {
        // ================= vertical chain =================
        const int idx   = bid * 8 + wrp;       // 0..4095
        const int plane = idx >> 3;
        const int tile  = idx & 7;
        const int c     = plane & (Cc - 1);

        float w1[5], w2[7];
#pragma unroll
        for (int j = 0; j < 5; j++) w1[j] = v1w[c * 5 + j];
#pragma unroll
        for (int k = 0; k < 7; k++) w2[k] = v2w[c * 7 + k];

        const float* xp = x + plane * PLANE + tile * 32 + l;
        __nv_bfloat16* vout = g_v + plane * PLANE + tile * 32 + l;

        float Y[21];
        float X[7];
#pragma unroll
        for (int i = 0; i < 21; i++) Y[i] = 0.f;

        float xv[11];
#pragma unroll
        for (int r = 0; r < 11; r++) xv[r] = xp[r * Ww];
#pragma unroll
        for (int ry = 0; ry < 9; ry++) {
            float s = 0.f;
#pragma unroll
            for (int j = 0; j < 5; j++) {
                int q = ry + j - 2;
                if (q >= 0) s += xv[q] * w1[j];
            }
            Y[ry] = s;
        }
#pragma unroll
        for (int r = 7; r < 11; r++) X[r % 7] = xv[r];

        float accg = 0.f;

#pragma unroll 1
        for (int sb = 0; sb < 273; sb += 21) {
#pragma unroll
            for (int u = 0; u < 21; u++) {
                const int s = sb + u;
                const int xrow = s + 11;
                float xn = xp[(xrow < 256 ? xrow : 255) * Ww];
                if (xrow > 255) xn = 0.f;
                X[(u + 4) % 7] = xn;
                float yv = X[(u + 0) % 7] * w1[0] + X[(u + 1) % 7] * w1[1]
                         + X[(u + 2) % 7] * w1[2] + X[(u + 3) % 7] * w1[3]
                         + X[(u + 4) % 7] * w1[4];
                if (s + 9 > 255) yv = 0.f;
                Y[(u + 9) % 21] = yv;
                float v = Y[(u + 12) % 21] * w2[0] + Y[(u + 15) % 21] * w2[1]
                        + Y[(u + 18) % 21] * w2[2] + Y[(u + 0)  % 21] * w2[3]
                        + Y[(u + 3)  % 21] * w2[4] + Y[(u + 6)  % 21] * w2[5]
                        + Y[(u + 9)  % 21] * w2[6];
                if (s < 256) {
                    vout[s * Ww] = __float2bfloat16(v);
                    accg += v;
                }
            }
        }

#pragma unroll
        for (int o = 16; o > 0; o >>= 1) accg += __shfl_down_sync(0xffffffffu, accg, o);
        if (l == 0) g_vpart[idx] = accg;
    } else {
        // ================= horizontal chain =================
        const int hb    = bid - 512;
        const int plane = hb >> 5;
        const int rb    = hb & 31;
        const int c     = plane & (Cc - 1);
        const int row   = rb * 8 + wrp;

        float w1[5], w2[7];
#pragma unroll
        for (int j = 0; j < 5; j++) w1[j] = h1w[c * 5 + j];
#pragma unroll
        for (int k = 0; k < 7; k++) w2[k] = h2w[c * 7 + k];

        const int base = plane * PLANE + row * Ww;

        *(float4*)&xs[wrp][12 + 4 * l]  = *(const float4*)(x + base + 4 * l);
        *(float4*)&xs[wrp][140 + 4 * l] = *(const float4*)(x + base + 128 + 4 * l);
        if (l < 3) {
            *(float4*)&xs[wrp][4 * l]       = make_float4(0.f, 0.f, 0.f, 0.f);
            *(float4*)&xs[wrp][268 + 4 * l] = make_float4(0.f, 0.f, 0.f, 0.f);
        }
        if (l < 9)  ys[wrp][l] = 0.f;
        if (l < 11) ys[wrp][265 + l] = 0.f;
        __syncwarp();

#pragma unroll
        for (int q = 0; q < 8; q++) {
            const int i = 9 + l + 32 * q;
            float y = 0.f;
#pragma unroll
            for (int j = 0; j < 5; j++) y += xs[wrp][i + 1 + j] * w1[j];
            ys[wrp][i] = y;
        }
        __syncwarp();

        float acc = 0.f;
#pragma unroll
        for (int q = 0; q < 8; q++) {
            const int px = l + 32 * q;
            float v = 0.f;
#pragma unroll
            for (int k = 0; k < 7; k++) v += ys[wrp][px + 3 * k] * w2[k];
            g_h[base + px] = __float2bfloat16(v);
            acc += v;
        }

#pragma unroll
        for (int o = 16; o > 0; o >>= 1) acc += __shfl_down_sync(0xffffffffu, acc, o);
        if (l == 0) red[wrp] = acc;
        __syncthreads();
        if (wrp == 0 && l == 0) {
            float s = 0.f;
#pragma unroll
            for (int i = 0; i < 8; i++) s += red[i];
            g_hpart[plane * 32 + rb] = s;
        }
    }
}

// ---------------------------------------------------------------------------
// Kernel 2: gate. One block, 256 threads.
// ---------------------------------------------------------------------------
__global__ __launch_bounds__(256) void gate_kernel(
    const float* __restrict__ g1w,
    const float* __restrict__ g2w,
    const float* __restrict__ g2b)
{
    __shared__ float pooled[Bb][2 * Cc];
    __shared__ float gs[Bb][32];
    const int t = threadIdx.x;
    const float inv = 1.0f / 65536.0f;

    for (int p = t; p < NPLANES; p += 256) {
        int b = p >> 7, c = p & 127;
        float hs = 0.f;
#pragma unroll
        for (int i = 0; i < 32; i++) hs += g_hpart[p * 32 + i];
        float vs = 0.f;
#pragma unroll
        for (int i = 0; i < 8; i++) vs += g_vpart[p * 8 + i];
        pooled[b][c]      = hs * inv;
        pooled[b][Cc + c] = vs * inv;
    }
    __syncthreads();

    if (t < 128) {
        int b = t >> 5, j = t & 31;
        float s = 0.f;
        for (int i = 0; i < 2 * Cc; i++) s += pooled[b][i] * g1w[j * 256 + i];
        gs[b][j] = s / (1.0f + expf(-s));
    }
    __syncthreads();

    if (t < Bb) {
        int b = t;
        float l0 = g2b[0], l1 = g2b[1];
        for (int j = 0; j < 32; j++) {
            l0 += gs[b][j] * g2w[j];
            l1 += gs[b][j] * g2w[32 + j];
        }
        float m = fmaxf(l0, l1);
        float e0 = expf(l0 - m), e1 = expf(l1 - m);
        float d = e0 + e1;
        g_gate[b * 2 + 0] = e0 / d;
        g_gate[b * 2 + 1] = e1 / d;
    }
}

// ---------------------------------------------------------------------------
// Kernel 3: bf16 HMMA fuse, high-occupancy version.
// CTA tile 128o x 64px, K=128; grid 4096; 8 warps, warp tile 32o x 32px
// (2x4 m16n8k16, acc = 32 regs). __launch_bounds__(256,3) -> 3 CTAs/SM so
// staging/MMA/epilogue phases of different CTAs overlap.
// Smem: wTs[128][136]bf16 (34816B) + as[128][72]bf16 (18432B) = 53248B;
// Dsm[128][68]f32 (34816B) reuses the same space for the epilogue.
// ---------------------------------------------------------------------------
#define FUSE_SMEM 53248

__global__ __launch_bounds__(256, 3) void fuse_mma_kernel(
    const float* __restrict__ x,
    const float* __restrict__ fw,
    const float* __restrict__ fb,
    float* __restrict__ out)
{
    extern __shared__ __align__(16) char smem[];
    __nv_bfloat16* wTs = (__nv_bfloat16*)smem;            // [128][136]
    __nv_bfloat16* as  = (__nv_bfloat16*)(smem + 34816);  // [128][72]
    float* Dsm = (float*)smem;                            // [128][68] (reuse)

    const int t   = threadIdx.x;
    const int wid = t >> 5;
    const int l   = t & 31;
    const int b   = blockIdx.x >> 10;
    const int p0  = (blockIdx.x & 1023) << 6;

    // ---- stage B = attn = wh*h + wv*v (issue global loads early)
    const float wh  = g_gate[2 * b + 0];
    const float wvv = g_gate[2 * b + 1];
    const int baseb = b * (Cc * PLANE) + p0;
#pragma unroll
    for (int it = 0; it < 4; it++) {
        const int i  = t + it * 256;          // 0..1023
        const int c  = i >> 3;
        const int px = (i & 7) << 3;
        const uint4 H = *(const uint4*)(g_h + baseb + c * PLANE + px);
        const uint4 V = *(const uint4*)(g_v + baseb + c * PLANE + px);
        const uint32_t* hp = &H.x;
        const uint32_t* vp = &V.x;
        uint32_t rr[4];
#pragma unroll
        for (int u = 0; u < 4; u++) {
            float2 hf = __bfloat1622float2(*(const __nv_bfloat162*)&hp[u]);
            float2 vf = __bfloat1622float2(*(const __nv_bfloat162*)&vp[u]);
            __nv_bfloat162 a2 = __floats2bfloat162_rn(wh * hf.x + wvv * vf.x,
                                                      wh * hf.y + wvv * vf.y);
            rr[u] = *(uint32_t*)&a2;
        }
        *(uint4*)(as + c * 72 + px) = make_uint4(rr[0], rr[1], rr[2], rr[3]);
    }

    // ---- stage A = fuse_w (fp32 -> bf16, row-major [o][c], pitch 136)
#pragma unroll
    for (int it = 0; it < 16; it++) {
        const int i  = t + it * 256;          // 0..4095
        const int o  = i >> 5;
        const int c4 = (i & 31) << 2;
        const float4 w4 = *(const float4*)(fw + o * 128 + c4);
        __nv_bfloat162 p01 = __floats2bfloat162_rn(w4.x, w4.y);
        __nv_bfloat162 p23 = __floats2bfloat162_rn(w4.z, w4.w);
        *(uint2*)(wTs + o * 136 + c4) =
            make_uint2(*(uint32_t*)&p01, *(uint32_t*)&p23);
    }
    __syncthreads();

    // ---- warp tile: og in {0,32,64,96}, pg in {0,32}
    const int og = (wid >> 1) * 32;
    const int pg = (wid & 1) * 32;

    float acc[2][4][4];
#pragma unroll
    for (int mi = 0; mi < 2; mi++)
#pragma unroll
        for (int ni = 0; ni < 4; ni++)
#pragma unroll
            for (int q = 0; q < 4; q++) acc[mi][ni][q] = 0.f;

    uint32_t aAddr[2], bAddr[4];
#pragma unroll
    for (int mi = 0; mi < 2; mi++)
        aAddr[mi] = smem_u32(wTs + (og + mi * 16 + (l & 15)) * 136 + (l >> 4) * 8);
#pragma unroll
    for (int ni = 0; ni < 4; ni++)
        bAddr[ni] = smem_u32(as + (l & 15) * 72 + pg + ni * 8);

#pragma unroll
    for (int kk = 0; kk < 8; kk++) {
        uint32_t a[2][4], bq[4][2];
#pragma unroll
        for (int mi = 0; mi < 2; mi++) {
            asm volatile("ldmatrix.sync.aligned.m8n8.x4.shared.b16 {%0,%1,%2,%3}, [%4];"
                : "=r"(a[mi][0]), "=r"(a[mi][1]), "=r"(a[mi][2]), "=r"(a[mi][3])
                : "r"(aAddr[mi] + kk * 32));
        }
#pragma unroll
        for (int ni = 0; ni < 4; ni++) {
            asm volatile("ldmatrix.sync.aligned.m8n8.x2.trans.shared.b16 {%0,%1}, [%2];"
                : "=r"(bq[ni][0]), "=r"(bq[ni][1])
                : "r"(bAddr[ni] + kk * 2304));   // 16 k-rows * 144 B
        }
#pragma unroll
        for (int mi = 0; mi < 2; mi++)
#pragma unroll
            for (int ni = 0; ni < 4; ni++) {
                asm volatile(
                    "mma.sync.aligned.m16n8k16.row.col.f32.bf16.bf16.f32 "
                    "{%0,%1,%2,%3}, {%4,%5,%6,%7}, {%8,%9}, {%0,%1,%2,%3};"
                    : "+f"(acc[mi][ni][0]), "+f"(acc[mi][ni][1]),
                      "+f"(acc[mi][ni][2]), "+f"(acc[mi][ni][3])
                    : "r"(a[mi][0]), "r"(a[mi][1]), "r"(a[mi][2]), "r"(a[mi][3]),
                      "r"(bq[ni][0]), "r"(bq[ni][1]));
            }
    }
    __syncthreads();   // done reading wTs/as; reuse smem as Dsm

    // ---- acc fragments -> Dsm (pitch 68)
#pragma unroll
    for (int mi = 0; mi < 2; mi++) {
        const int row = og + mi * 16 + (l >> 2);
#pragma unroll
        for (int ni = 0; ni < 4; ni++) {
            const int col = pg + ni * 8 + (l & 3) * 2;
            *(float2*)(Dsm + row * 68 + col) =
                make_float2(acc[mi][ni][0], acc[mi][ni][1]);
            *(float2*)(Dsm + (row + 8) * 68 + col) =
                make_float2(acc[mi][ni][2], acc[mi][ni][3]);
        }
    }
    __syncthreads();

    // ---- epilogue: out = x * (0.5 + 0.5*(d + fb[o])); 2 rows/warp/iter
    const int px4 = (l & 15) * 4;
#pragma unroll
    for (int it = 0; it < 8; it++) {
        const int o = wid * 16 + it * 2 + (l >> 4);
        const float4 d4 = *(const float4*)(Dsm + o * 68 + px4);
        const float fbv = fb[o];
        const int idx = b * (Cc * PLANE) + o * PLANE + p0 + px4;
        const float4 xv = *(const float4*)(x + idx);
        float4 r;
        r.x = xv.x * (0.5f + 0.5f * (d4.x + fbv));
        r.y = xv.y * (0.5f + 0.5f * (d4.y + fbv));
        r.z = xv.z * (0.5f + 0.5f * (d4.z + fbv));
        r.w = xv.w * (0.5f + 0.5f * (d4.w + fbv));
        *(float4*)(out + idx) = r;
    }
}

// ---------------------------------------------------------------------------
extern "C" void kernel_launch(void* const* d_in, const int* in_sizes, int n_in,
                              void* d_out, int out_size)
{
    const float* x   = (const float*)d_in[0];
    const float* h1w = (const float*)d_in[1];
    const float* h2w = (const float*)d_in[2];
    const float* v1w = (const float*)d_in[3];
    const float* v2w = (const float*)d_in[4];
    const float* g1w = (const float*)d_in[5];
    const float* g2w = (const float*)d_in[6];
    const float* g2b = (const float*)d_in[7];
    const float* fw  = (const float*)d_in[8];
    const float* fb  = (const float*)d_in[9];
    float* out = (float*)d_out;

    cudaFuncSetAttribute(fuse_mma_kernel, cudaFuncAttributeMaxDynamicSharedMemorySize, FUSE_SMEM);

    conv_kernel<<<16896, 256>>>(x, h1w, h2w, v1w, v2w);
    gate_kernel<<<1, 256>>>(g1w, g2w, g2b);
    fuse_mma_kernel<<<4096, 256, FUSE_SMEM>>>(x, fw, fb, out);
}

// round 16
// speedup vs baseline: 2.2454x; 1.0040x over previous
#include <cuda_runtime.h>
#include <cuda_bf16.h>
#include <cstdint>

// Problem constants
#define Cc      128
#define Hh      256
#define Ww      256
#define Bb      4
#define PLANE   65536
#define NPLANES 512
#define TOTAL   33554432

// Scratch (allocation-free rule: __device__ globals). 16B-aligned for uint4 IO.
__device__ __align__(16) __nv_bfloat16 g_h[TOTAL];
__device__ __align__(16) __nv_bfloat16 g_v[TOTAL];
__device__ float  g_hpart[NPLANES * 32];
__device__ float  g_vpart[NPLANES * 8];
__device__ float  g_gate[Bb * 2];

__device__ __forceinline__ uint32_t smem_u32(const void* p) {
    uint32_t a;
    asm("{ .reg .u64 t; cvta.to.shared.u64 t, %1; cvt.u32.u64 %0, t; }" : "=r"(a) : "l"(p));
    return a;
}

// ---------------------------------------------------------------------------
// Kernel 1: COMBINED directional convs.
// Blocks [0,512): vertical chain (register sliding windows, LDG/FFMA-bound).
// Blocks [512,16896): horizontal chain — NEW: pure registers + warp shuffles,
// zero smem in the hot path (kills the 68.9% L1 ceiling from R12).
// Lane l owns 8 contiguous px; inter-stage zero-padding reproduced exactly.
// ---------------------------------------------------------------------------
__global__ __launch_bounds__(256) void conv_kernel(
    const float* __restrict__ x,
    const float* __restrict__ h1w,
    const float* __restrict__ h2w,
    const float* __restrict__ v1w,
    const float* __restrict__ v2w)
{
    __shared__ float red[8];

    const int bid = blockIdx.x;
    const int t   = threadIdx.x;
    const int l   = t & 31;
    const int wrp = t >> 5;
    const unsigned FULL = 0xffffffffu;

    if (bid < 512) {
        // ================= vertical chain (unchanged) =================
        const int idx   = bid * 8 + wrp;       // 0..4095
        const int plane = idx >> 3;
        const int tile  = idx & 7;
        const int c     = plane & (Cc - 1);

        float w1[5], w2[7];
#pragma unroll
        for (int j = 0; j < 5; j++) w1[j] = v1w[c * 5 + j];
#pragma unroll
        for (int k = 0; k < 7; k++) w2[k] = v2w[c * 7 + k];

        const float* xp = x + plane * PLANE + tile * 32 + l;
        __nv_bfloat16* vout = g_v + plane * PLANE + tile * 32 + l;

        float Y[21];
        float X[7];
#pragma unroll
        for (int i = 0; i < 21; i++) Y[i] = 0.f;

        float xv[11];
#pragma unroll
        for (int r = 0; r < 11; r++) xv[r] = xp[r * Ww];
#pragma unroll
        for (int ry = 0; ry < 9; ry++) {
            float s = 0.f;
#pragma unroll
            for (int j = 0; j < 5; j++) {
                int q = ry + j - 2;
                if (q >= 0) s += xv[q] * w1[j];
            }
            Y[ry] = s;
        }
#pragma unroll
        for (int r = 7; r < 11; r++) X[r % 7] = xv[r];

        float accg = 0.f;

#pragma unroll 1
        for (int sb = 0; sb < 273; sb += 21) {
#pragma unroll
            for (int u = 0; u < 21; u++) {
                const int s = sb + u;
                const int xrow = s + 11;
                float xn = xp[(xrow < 256 ? xrow : 255) * Ww];
                if (xrow > 255) xn = 0.f;
                X[(u + 4) % 7] = xn;
                float yv = X[(u + 0) % 7] * w1[0] + X[(u + 1) % 7] * w1[1]
                         + X[(u + 2) % 7] * w1[2] + X[(u + 3) % 7] * w1[3]
                         + X[(u + 4) % 7] * w1[4];
                if (s + 9 > 255) yv = 0.f;
                Y[(u + 9) % 21] = yv;
                float v = Y[(u + 12) % 21] * w2[0] + Y[(u + 15) % 21] * w2[1]
                        + Y[(u + 18) % 21] * w2[2] + Y[(u + 0)  % 21] * w2[3]
                        + Y[(u + 3)  % 21] * w2[4] + Y[(u + 6)  % 21] * w2[5]
                        + Y[(u + 9)  % 21] * w2[6];
                if (s < 256) {
                    vout[s * Ww] = __float2bfloat16(v);
                    accg += v;
                }
            }
        }

#pragma unroll
        for (int o = 16; o > 0; o >>= 1) accg += __shfl_down_sync(FULL, accg, o);
        if (l == 0) g_vpart[idx] = accg;
    } else {
        // ========== horizontal chain: registers + shuffles, no smem ==========
        const int hb    = bid - 512;
        const int plane = hb >> 5;
        const int rb    = hb & 31;
        const int c     = plane & (Cc - 1);
        const int row   = rb * 8 + wrp;

        float w1[5], w2[7];
#pragma unroll
        for (int j = 0; j < 5; j++) w1[j] = h1w[c * 5 + j];
#pragma unroll
        for (int k = 0; k < 7; k++) w2[k] = h2w[c * 7 + k];

        const int base = plane * PLANE + row * Ww;

        // lane l holds x[8l .. 8l+7]
        float xr[8];
        {
            const float4 a = *(const float4*)(x + base + 8 * l);
            const float4 bq = *(const float4*)(x + base + 8 * l + 4);
            xr[0] = a.x; xr[1] = a.y; xr[2] = a.z; xr[3] = a.w;
            xr[4] = bq.x; xr[5] = bq.y; xr[6] = bq.z; xr[7] = bq.w;
        }

        // stage-1 halo: x[8l-2], x[8l-1] from lane l-1; x[8l+8], x[8l+9] from l+1
        float xm2 = __shfl_up_sync(FULL, xr[6], 1);
        float xm1 = __shfl_up_sync(FULL, xr[7], 1);
        float xp1 = __shfl_down_sync(FULL, xr[0], 1);
        float xp2 = __shfl_down_sync(FULL, xr[1], 1);
        if (l == 0)  { xm2 = 0.f; xm1 = 0.f; }
        if (l == 31) { xp1 = 0.f; xp2 = 0.f; }

        // stage 1: y[i] = sum_j x[i-2+j] * w1[j]
        float y[8];
#pragma unroll
        for (int i = 0; i < 8; i++) {
            float s = 0.f;
#pragma unroll
            for (int j = 0; j < 5; j++) {
                const int o = i - 2 + j;
                const float xv = (o < 0) ? (o == -2 ? xm2 : xm1)
                               : (o > 7) ? (o == 8 ? xp1 : xp2)
                               : xr[o];
                s += xv * w1[j];
            }
            y[i] = s;
        }

        // stage-2 halo: Lm[j] = y[8l-9+j] (j=0..8), Rt[j] = y[8l+8+j] (j=0..8)
        float Lm[9], Rt[9];
        Lm[0] = __shfl_up_sync(FULL, y[7], 2);
#pragma unroll
        for (int j = 1; j < 9; j++) Lm[j] = __shfl_up_sync(FULL, y[j - 1], 1);
#pragma unroll
        for (int j = 0; j < 8; j++) Rt[j] = __shfl_down_sync(FULL, y[j], 1);
        Rt[8] = __shfl_down_sync(FULL, y[0], 2);
        if (l < 2) Lm[0] = 0.f;
        if (l < 1) {
#pragma unroll
            for (int j = 1; j < 9; j++) Lm[j] = 0.f;
        }
        if (l > 30) {
#pragma unroll
            for (int j = 0; j < 8; j++) Rt[j] = 0.f;
        }
        if (l > 29) Rt[8] = 0.f;

        // stage 2: h[i] = sum_k Y(i-9+3k) * w2[k]   (Y zero-padded outside [0,256))
        float hv[8];
        float acc = 0.f;
#pragma unroll
        for (int i = 0; i < 8; i++) {
            float s = 0.f;
#pragma unroll
            for (int k = 0; k < 7; k++) {
                const int off = i - 9 + 3 * k;
                const float yv = (off < 0) ? Lm[off + 9]
                               : (off < 8) ? y[off]
                               : Rt[off - 8];
                s += yv * w2[k];
            }
            hv[i] = s;
            acc += s;
        }

        // coalesced bf16x8 store (16B per lane)
        {
            __nv_bfloat162 p0 = __floats2bfloat162_rn(hv[0], hv[1]);
            __nv_bfloat162 p1 = __floats2bfloat162_rn(hv[2], hv[3]);
            __nv_bfloat162 p2 = __floats2bfloat162_rn(hv[4], hv[5]);
            __nv_bfloat162 p3 = __floats2bfloat162_rn(hv[6], hv[7]);
            uint4 st;
            st.x = *(uint32_t*)&p0; st.y = *(uint32_t*)&p1;
            st.z = *(uint32_t*)&p2; st.w = *(uint32_t*)&p3;
            *(uint4*)(g_h + base + 8 * l) = st;
        }

        // warp reduce + tiny cross-warp combine for the gate partial
#pragma unroll
        for (int o = 16; o > 0; o >>= 1) acc += __shfl_down_sync(FULL, acc, o);
        if (l == 0) red[wrp] = acc;
        __syncthreads();
        if (wrp == 0 && l == 0) {
            float s = 0.f;
#pragma unroll
            for (int i = 0; i < 8; i++) s += red[i];
            g_hpart[plane * 32 + rb] = s;
        }
    }
}

// ---------------------------------------------------------------------------
// Kernel 2: gate. One block, 256 threads.
// ---------------------------------------------------------------------------
__global__ __launch_bounds__(256) void gate_kernel(
    const float* __restrict__ g1w,
    const float* __restrict__ g2w,
    const float* __restrict__ g2b)
{
    __shared__ float pooled[Bb][2 * Cc];
    __shared__ float gs[Bb][32];
    const int t = threadIdx.x;
    const float inv = 1.0f / 65536.0f;

    for (int p = t; p < NPLANES; p += 256) {
        int b = p >> 7, c = p & 127;
        float hs = 0.f;
#pragma unroll
        for (int i = 0; i < 32; i++) hs += g_hpart[p * 32 + i];
        float vs = 0.f;
#pragma unroll
        for (int i = 0; i < 8; i++) vs += g_vpart[p * 8 + i];
        pooled[b][c]      = hs * inv;
        pooled[b][Cc + c] = vs * inv;
    }
    __syncthreads();

    if (t < 128) {
        int b = t >> 5, j = t & 31;
        float s = 0.f;
        for (int i = 0; i < 2 * Cc; i++) s += pooled[b][i] * g1w[j * 256 + i];
        gs[b][j] = s / (1.0f + expf(-s));
    }
    __syncthreads();

    if (t < Bb) {
        int b = t;
        float l0 = g2b[0], l1 = g2b[1];
        for (int j = 0; j < 32; j++) {
            l0 += gs[b][j] * g2w[j];
            l1 += gs[b][j] * g2w[32 + j];
        }
        float m = fmaxf(l0, l1);
        float e0 = expf(l0 - m), e1 = expf(l1 - m);
        float d = e0 + e1;
        g_gate[b * 2 + 0] = e0 / d;
        g_gate[b * 2 + 1] = e1 / d;
    }
}

// ---------------------------------------------------------------------------
// Kernel 3: bf16 HMMA fuse (unchanged from R12 — passing, ~104us).
// CTA tile 128o x 64px, K=128; grid 4096; 3 CTAs/SM.
// ---------------------------------------------------------------------------
#define FUSE_SMEM 53248

__global__ __launch_bounds__(256, 3) void fuse_mma_kernel(
    const float* __restrict__ x,
    const float* __restrict__ fw,
    const float* __restrict__ fb,
    float* __restrict__ out)
{
    extern __shared__ __align__(16) char smem[];
    __nv_bfloat16* wTs = (__nv_bfloat16*)smem;            // [128][136]
    __nv_bfloat16* as  = (__nv_bfloat16*)(smem + 34816);  // [128][72]
    float* Dsm = (float*)smem;                            // [128][68] (reuse)

    const int t   = threadIdx.x;
    const int wid = t >> 5;
    const int l   = t & 31;
    const int b   = blockIdx.x >> 10;
    const int p0  = (blockIdx.x & 1023) << 6;

    const float wh  = g_gate[2 * b + 0];
    const float wvv = g_gate[2 * b + 1];
    const int baseb = b * (Cc * PLANE) + p0;
#pragma unroll
    for (int it = 0; it < 4; it++) {
        const int i  = t + it * 256;
        const int c  = i >> 3;
        const int px = (i & 7) << 3;
        const uint4 H = *(const uint4*)(g_h + baseb + c * PLANE + px);
        const uint4 V = *(const uint4*)(g_v + baseb + c * PLANE + px);
        const uint32_t* hp = &H.x;
        const uint32_t* vp = &V.x;
        uint32_t rr[4];
#pragma unroll
        for (int u = 0; u < 4; u++) {
            float2 hf = __bfloat1622float2(*(const __nv_bfloat162*)&hp[u]);
            float2 vf = __bfloat1622float2(*(const __nv_bfloat162*)&vp[u]);
            __nv_bfloat162 a2 = __floats2bfloat162_rn(wh * hf.x + wvv * vf.x,
                                                      wh * hf.y + wvv * vf.y);
            rr[u] = *(uint32_t*)&a2;
        }
        *(uint4*)(as + c * 72 + px) = make_uint4(rr[0], rr[1], rr[2], rr[3]);
    }

#pragma unroll
    for (int it = 0; it < 16; it++) {
        const int i  = t + it * 256;
        const int o  = i >> 5;
        const int c4 = (i & 31) << 2;
        const float4 w4 = *(const float4*)(fw + o * 128 + c4);
        __nv_bfloat162 p01 = __floats2bfloat162_rn(w4.x, w4.y);
        __nv_bfloat162 p23 = __floats2bfloat162_rn(w4.z, w4.w);
        *(uint2*)(wTs + o * 136 + c4) =
            make_uint2(*(uint32_t*)&p01, *(uint32_t*)&p23);
    }
    __syncthreads();

    const int og = (wid >> 1) * 32;
    const int pg = (wid & 1) * 32;

    float acc[2][4][4];
#pragma unroll
    for (int mi = 0; mi < 2; mi++)
#pragma unroll
        for (int ni = 0; ni < 4; ni++)
#pragma unroll
            for (int q = 0; q < 4; q++) acc[mi][ni][q] = 0.f;

    uint32_t aAddr[2], bAddr[4];
#pragma unroll
    for (int mi = 0; mi < 2; mi++)
        aAddr[mi] = smem_u32(wTs + (og + mi * 16 + (l & 15)) * 136 + (l >> 4) * 8);
#pragma unroll
    for (int ni = 0; ni < 4; ni++)
        bAddr[ni] = smem_u32(as + (l & 15) * 72 + pg + ni * 8);

#pragma unroll
    for (int kk = 0; kk < 8; kk++) {
        uint32_t a[2][4], bq[4][2];
#pragma unroll
        for (int mi = 0; mi < 2; mi++) {
            asm volatile("ldmatrix.sync.aligned.m8n8.x4.shared.b16 {%0,%1,%2,%3}, [%4];"
                : "=r"(a[mi][0]), "=r"(a[mi][1]), "=r"(a[mi][2]), "=r"(a[mi][3])
                : "r"(aAddr[mi] + kk * 32));
        }
#pragma unroll
        for (int ni = 0; ni < 4; ni++) {
            asm volatile("ldmatrix.sync.aligned.m8n8.x2.trans.shared.b16 {%0,%1}, [%2];"
                : "=r"(bq[ni][0]), "=r"(bq[ni][1])
                : "r"(bAddr[ni] + kk * 2304));
        }
#pragma unroll
        for (int mi = 0; mi < 2; mi++)
#pragma unroll
            for (int ni = 0; ni < 4; ni++) {
                asm volatile(
                    "mma.sync.aligned.m16n8k16.row.col.f32.bf16.bf16.f32 "
                    "{%0,%1,%2,%3}, {%4,%5,%6,%7}, {%8,%9}, {%0,%1,%2,%3};"
                    : "+f"(acc[mi][ni][0]), "+f"(acc[mi][ni][1]),
                      "+f"(acc[mi][ni][2]), "+f"(acc[mi][ni][3])
                    : "r"(a[mi][0]), "r"(a[mi][1]), "r"(a[mi][2]), "r"(a[mi][3]),
                      "r"(bq[ni][0]), "r"(bq[ni][1]));
            }
    }
    __syncthreads();

#pragma unroll
    for (int mi = 0; mi < 2; mi++) {
        const int row = og + mi * 16 + (l >> 2);
#pragma unroll
        for (int ni = 0; ni < 4; ni++) {
            const int col = pg + ni * 8 + (l & 3) * 2;
            *(float2*)(Dsm + row * 68 + col) =
                make_float2(acc[mi][ni][0], acc[mi][ni][1]);
            *(float2*)(Dsm + (row + 8) * 68 + col) =
                make_float2(acc[mi][ni][2], acc[mi][ni][3]);
        }
    }
    __syncthreads();

    const int px4 = (l & 15) * 4;
#pragma unroll
    for (int it = 0; it < 8; it++) {
        const int o = wid * 16 + it * 2 + (l >> 4);
        const float4 d4 = *(const float4*)(Dsm + o * 68 + px4);
        const float fbv = fb[o];
        const int idx = b * (Cc * PLANE) + o * PLANE + p0 + px4;
        const float4 xv = *(const float4*)(x + idx);
        float4 r;
        r.x = xv.x * (0.5f + 0.5f * (d4.x + fbv));
        r.y = xv.y * (0.5f + 0.5f * (d4.y + fbv));
        r.z = xv.z * (0.5f + 0.5f * (d4.z + fbv));
        r.w = xv.w * (0.5f + 0.5f * (d4.w + fbv));
        *(float4*)(out + idx) = r;
    }
}

// ---------------------------------------------------------------------------
extern "C" void kernel_launch(void* const* d_in, const int* in_sizes, int n_in,
                              void* d_out, int out_size)
{
    const float* x   = (const float*)d_in[0];
    const float* h1w = (const float*)d_in[1];
    const float* h2w = (const float*)d_in[2];
    const float* v1w = (const float*)d_in[3];
    const float* v2w = (const float*)d_in[4];
    const float* g1w = (const float*)d_in[5];
    const float* g2w = (const float*)d_in[6];
    const float* g2b = (const float*)d_in[7];
    const float* fw  = (const float*)d_in[8];
    const float* fb  = (const float*)d_in[9];
    float* out = (float*)d_out;

    cudaFuncSetAttribute(fuse_mma_kernel, cudaFuncAttributeMaxDynamicSharedMemorySize, FUSE_SMEM);

    conv_kernel<<<16896, 256>>>(x, h1w, h2w, v1w, v2w);
    gate_kernel<<<1, 256>>>(g1w, g2w, g2b);
    fuse_mma_kernel<<<4096, 256, FUSE_SMEM>>>(x, fw, fb, out);
}